// round 7
// baseline (speedup 1.0000x reference)
#include <cuda_runtime.h>
#include <cstdint>

#define TILE_WORDS 8192
#define NTHREADS   512
#define NWARPS     (NTHREADS / 32)
#define GRID_CTAS  456              // 152 SMs * 3 CTAs
#define VECS_PER_LANE  (TILE_WORDS / 32 / 4)   // 64 uint4 per lane per tile
#define BATCH      4                 // loads in flight per lane
#define NBLKS      (VECS_PER_LANE / BATCH)     // 16

// constants from the reference
#define FMIX_C1 2246822507u
#define FMIX_C2 3266489909u
#define POS_A   668265261u
#define POS_B   374761393u
#define SEED    608135816u

__device__ unsigned int g_tile_counter;

__global__ void reset_counter_kernel() { g_tile_counter = 0u; }

__device__ __forceinline__ uint32_t fmix32(uint32_t x) {
    x ^= x >> 16;
    x *= FMIX_C1;
    x ^= x >> 13;
    x *= FMIX_C2;
    x ^= x >> 16;
    return x;
}

// one word, two independent hash streams
__device__ __forceinline__ void hash_step(uint32_t v, uint32_t i,
                                          uint32_t s1, uint32_t s2,
                                          uint32_t& h1, uint32_t& h2) {
    // p = (i*POS + s) ^ rotl(i, r); v ^ a ^ r fuses into one LOP3
    uint32_t a1 = i * POS_A + s1;
    uint32_t r1 = __funnelshift_l(i, i, 15);
    uint32_t a2 = i * POS_B + s2;
    uint32_t r2 = __funnelshift_l(i, i, 13);
    h1 += fmix32(v ^ a1 ^ r1);
    h2 += fmix32(v ^ a2 ^ r2);
}

__global__ void __launch_bounds__(NTHREADS, 3)
hash_tiles_kernel(const uint32_t* __restrict__ in,
                  float* __restrict__ out,
                  uint32_t n, uint32_t n_tiles) {
    const uint32_t lane = threadIdx.x & 31u;
    const uint32_t s1 = SEED;
    const uint32_t s2 = (uint32_t)((SEED * 2654435761u) ^ 3735928559u);
    const uint32_t nbytes = n * 4u;   // wrapping

    for (;;) {
        // warp steals next tile
        uint32_t t;
        if (lane == 0u) t = atomicAdd(&g_tile_counter, 1u);
        t = __shfl_sync(0xffffffffu, t, 0);
        if (t >= n_tiles) break;

        const uint32_t base = t * TILE_WORDS;
        uint32_t h1 = 0u, h2 = 0u;

        if (base + TILE_WORDS <= n) {
            // full tile: 64 coalesced uint4 per lane, 4-deep load batches
            const uint4* inv = reinterpret_cast<const uint4*>(in + base);
            #pragma unroll 4
            for (int blk = 0; blk < NBLKS; ++blk) {
                uint4 v[BATCH];
                #pragma unroll
                for (int u = 0; u < BATCH; ++u) {
                    v[u] = __ldcs(&inv[(uint32_t)(blk * BATCH + u) * 32u + lane]);
                }
                #pragma unroll
                for (int u = 0; u < BATCH; ++u) {
                    uint32_t i0 = base + ((uint32_t)(blk * BATCH + u) * 32u + lane) * 4u;
                    hash_step(v[u].x, i0 + 0u, s1, s2, h1, h2);
                    hash_step(v[u].y, i0 + 1u, s1, s2, h1, h2);
                    hash_step(v[u].z, i0 + 2u, s1, s2, h1, h2);
                    hash_step(v[u].w, i0 + 3u, s1, s2, h1, h2);
                }
            }
        } else {
            // ragged tail tile: scalar guarded (not hit for n % TILE == 0)
            for (uint32_t w = lane; w < TILE_WORDS; w += 32u) {
                uint32_t i = base + w;
                if (i < n) hash_step(in[i], i, s1, s2, h1, h2);
            }
        }

        // warp-only reduction (wrapping uint32 adds); no smem, no block sync
        #pragma unroll
        for (int o = 16; o > 0; o >>= 1) {
            h1 += __shfl_down_sync(0xffffffffu, h1, o);
            h2 += __shfl_down_sync(0xffffffffu, h2, o);
        }

        if (lane == 0u) {
            uint32_t a = fmix32(h1 ^ nbytes);   // high word of int64 hash
            uint32_t b = fmix32(h2 ^ nbytes);   // low word of int64 hash
            (void)a;
            // Output = int64 hash truncated to int32 (low word = h2_final),
            // value-cast to float32. Verified bit-exact in R5.
            out[t] = (float)(int32_t)b;
        }
    }
}

extern "C" void kernel_launch(void* const* d_in, const int* in_sizes, int n_in,
                              void* d_out, int out_size) {
    const uint32_t* in = (const uint32_t*)d_in[0];
    float* out = (float*)d_out;
    uint32_t n = (uint32_t)in_sizes[0];
    uint32_t n_tiles = (n + TILE_WORDS - 1) / TILE_WORDS;
    reset_counter_kernel<<<1, 1>>>();
    hash_tiles_kernel<<<GRID_CTAS, NTHREADS>>>(in, out, n, n_tiles);
}

// round 8
// speedup vs baseline: 1.7240x; 1.7240x over previous
#include <cuda_runtime.h>
#include <cstdint>

#define TILE_WORDS 8192
#define NTHREADS   512
#define WPT        (TILE_WORDS / NTHREADS)   // 16 words per thread
#define VECS       (WPT / 4)                 // 4 uint4 per thread
#define NWARPS     (NTHREADS / 32)

// constants from the reference (only the h2 stream survives to the output)
#define FMIX_C1 2246822507u
#define FMIX_C2 3266489909u
#define POS_B   374761393u
#define SEED    608135816u

__device__ __forceinline__ uint32_t fmix32(uint32_t x) {
    x ^= x >> 16;
    x *= FMIX_C1;
    x ^= x >> 13;
    x *= FMIX_C2;
    x ^= x >> 16;
    return x;
}

// One word, h2 stream ONLY. The output is the int64 hash truncated to int32,
// i.e. the low word = h2_final — the h1 stream is provably dead (rel_err=0
// since R5) and is removed to halve integer-ALU work.
__device__ __forceinline__ void hash_step(uint32_t v, uint32_t i,
                                          uint32_t s2, uint32_t& h2) {
    uint32_t a2 = i * POS_B + s2;                 // IMAD
    uint32_t r2 = __funnelshift_l(i, i, 13);      // SHF (rotl 13)
    h2 += fmix32(v ^ a2 ^ r2);                    // LOP3 fuses v^a^r
}

__global__ void __launch_bounds__(NTHREADS, 3)
hash_tiles_kernel(const uint32_t* __restrict__ in,
                  float* __restrict__ out,
                  uint32_t n) {
    const uint32_t tile = blockIdx.x;
    const uint32_t base = tile * TILE_WORDS;
    const uint32_t tid  = threadIdx.x;

    const uint32_t s2 = (uint32_t)((SEED * 2654435761u) ^ 3735928559u);

    uint32_t h2 = 0u;

    if (base + TILE_WORDS <= n) {
        // fast path: full tile; 4 coalesced uint4 loads per thread, batched up
        // front (evict-first: data is single-touch streaming)
        const uint4* inv = reinterpret_cast<const uint4*>(in + base);
        uint4 v[VECS];
        #pragma unroll
        for (int j = 0; j < VECS; ++j) {
            v[j] = __ldcs(&inv[(uint32_t)j * NTHREADS + tid]);
        }
        #pragma unroll
        for (int j = 0; j < VECS; ++j) {
            uint32_t i0 = base + ((uint32_t)j * NTHREADS + tid) * 4u;
            hash_step(v[j].x, i0 + 0u, s2, h2);
            hash_step(v[j].y, i0 + 1u, s2, h2);
            hash_step(v[j].z, i0 + 2u, s2, h2);
            hash_step(v[j].w, i0 + 3u, s2, h2);
        }
    } else {
        // ragged tail tile: scalar guarded (not hit for n % TILE == 0)
        for (uint32_t w = tid; w < TILE_WORDS; w += NTHREADS) {
            uint32_t i = base + w;
            if (i < n) hash_step(in[i], i, s2, h2);
        }
    }

    // warp reduction (wrapping uint32 adds)
    #pragma unroll
    for (int o = 16; o > 0; o >>= 1) {
        h2 += __shfl_down_sync(0xffffffffu, h2, o);
    }

    __shared__ uint32_t sh2[NWARPS];
    if ((tid & 31u) == 0u) sh2[tid >> 5] = h2;
    __syncthreads();

    if (tid == 0) {
        uint32_t b = 0u;
        #pragma unroll
        for (int w = 0; w < NWARPS; ++w) b += sh2[w];
        uint32_t nbytes = n * 4u;          // wrapping, matches (n*4) & 0xFFFFFFFF
        b = fmix32(b ^ nbytes);            // h2_final = low word of int64 hash
        // Output = int64 hash truncated to int32, value-cast to float32.
        out[tile] = (float)(int32_t)b;
    }
}

extern "C" void kernel_launch(void* const* d_in, const int* in_sizes, int n_in,
                              void* d_out, int out_size) {
    const uint32_t* in = (const uint32_t*)d_in[0];
    float* out = (float*)d_out;
    uint32_t n = (uint32_t)in_sizes[0];
    uint32_t n_tiles = (n + TILE_WORDS - 1) / TILE_WORDS;
    hash_tiles_kernel<<<n_tiles, NTHREADS>>>(in, out, n);
}